// round 4
// baseline (speedup 1.0000x reference)
#include <cuda_runtime.h>
#include <cstdint>
#include <math.h>

#define BATCH 4
#define CDIM 384
#define HDIM 128
#define WDIM 128
#define HW 16384
#define HEADS 8
#define CH 48
#define NPLANE (BATCH*CDIM)
#define NELEM (BATCH*CDIM*HW)
#define NB64 (HW/64)        // 256 n-blocks of 64

// ---------------- static device scratch (no cudaMalloc allowed) -------------
__device__ float g_bufA[NELEM];      // gemm output (std)
__device__ float g_bufB[NELEM];      // dw temp / k std
__device__ float g_bufC[NELEM];      // v std
__device__ float g_bufD[NELEM];      // q std
__device__ float g_Xf[NELEM];        // x fragment-major tf32
__device__ float g_Tf[NELEM];        // t fragment-major tf32
__device__ float g_QQf[2*NELEM];     // concat(q1,q2) fragment-major tf32 (K=768)
__device__ float g_Wf[4*CDIM*CDIM + CDIM*2*CDIM];  // all weight fragments
__device__ float g_norms[2*NPLANE];
__device__ float g_gpart[16*32*CH*CH];
__device__ float g_attn[32*CH*CH];

// Wf offsets (floats)
#define WOFF_Q    0
#define WOFF_QT   (CDIM*CDIM)
#define WOFF_QCAT (2*CDIM*CDIM)
#define WOFF_K    (2*CDIM*CDIM + CDIM*2*CDIM)
#define WOFF_V    (3*CDIM*CDIM + CDIM*2*CDIM)

// ---------------- helpers ---------------------------------------------------
__device__ __forceinline__ float f2tf32f(float x){
    uint32_t u;
    asm("cvt.rna.tf32.f32 %0, %1;" : "=r"(u) : "f"(x));
    return __uint_as_float(u);
}
__device__ __forceinline__ void mma_tf32(float* c, float a0, float a1,
                                         float a2, float a3,
                                         float b0, float b1){
    asm volatile(
        "mma.sync.aligned.m16n8k8.row.col.f32.tf32.tf32.f32 "
        "{%0,%1,%2,%3}, {%4,%5,%6,%7}, {%8,%9}, {%0,%1,%2,%3};"
        : "+f"(c[0]), "+f"(c[1]), "+f"(c[2]), "+f"(c[3])
        : "r"(__float_as_uint(a0)), "r"(__float_as_uint(a1)),
          "r"(__float_as_uint(a2)), "r"(__float_as_uint(a3)),
          "r"(__float_as_uint(b0)), "r"(__float_as_uint(b1)));
}

// ---------------------------------------------------------------------------
// Weight -> A-fragment layout (tf32 rounded).
// Af[((k8*Mblks + mb)*32 + lane)*16 + v],  v = mt*4 + s:
//   row = mb*64 + mt*16 + (lane>>2) + (s&1)*8
//   col = k8*8  + (lane&3) + ((s>>1)&1)*4
// grid = (K/8, M/64), block = 32
// ---------------------------------------------------------------------------
__global__ void prep_w_k(const float* __restrict__ W, int ldk, int Mblks,
                         float* __restrict__ Af)
{
    const int k8 = blockIdx.x, mb = blockIdx.y, lane = threadIdx.x;
    float v[16];
#pragma unroll
    for (int i = 0; i < 16; i++){
        int mt = i >> 2, s = i & 3;
        int row = mb * 64 + mt * 16 + (lane >> 2) + (s & 1) * 8;
        int col = k8 * 8 + (lane & 3) + ((s >> 1) & 1) * 4;
        v[i] = f2tf32f(W[(size_t)row * ldk + col]);
    }
    float4* dst = reinterpret_cast<float4*>(
        Af + (((size_t)k8 * Mblks + mb) * 32 + lane) * 16);
#pragma unroll
    for (int q = 0; q < 4; q++)
        dst[q] = make_float4(v[q*4], v[q*4+1], v[q*4+2], v[q*4+3]);
}

// ---------------------------------------------------------------------------
// Std [K'][HW] (per batch) -> B-fragment layout (tf32 rounded).
// Bf[((k8g*NB64 + nb)*32 + lane)*16 + v], v = nt*2 + j:
//   k = k8g*8 + (lane&3) + j*4   (k8g = k8base + local)
//   n = nb*64 + nt*8 + (lane>>2)
// Block handles one k8 slab x 512 cols. grid = (HW/512, K'/8, BATCH), blk 256.
// ---------------------------------------------------------------------------
__global__ __launch_bounds__(256) void prep_bfrag_k(
    const float* __restrict__ src, int Ksrc,
    float* __restrict__ Bf, int Kdst, int k8base)
{
    __shared__ float s[8 * 520];
    const int tid = threadIdx.x;
    const int z = blockIdx.z;
    const int k8l = blockIdx.y;
    const int n0 = blockIdx.x * 512;
    const float* sp = src + (size_t)z * Ksrc * HW + (size_t)(k8l * 8) * HW + n0;

#pragma unroll
    for (int i = 0; i < 4; i++){
        int f = tid + i * 256;       // 1024 float4
        int r = f >> 7;
        int c4 = (f & 127) << 2;
        *reinterpret_cast<float4*>(&s[r * 520 + c4]) =
            *reinterpret_cast<const float4*>(&sp[(size_t)r * HW + c4]);
    }
    __syncthreads();

    const int w = tid >> 5, lane = tid & 31;
    const int k8g = k8base + k8l;
    const int nb = (n0 >> 6) + w;
    float v[16];
#pragma unroll
    for (int i = 0; i < 16; i++){
        int nt = i >> 1, j = i & 1;
        v[i] = f2tf32f(s[((lane & 3) + j * 4) * 520 + w * 64 + nt * 8 + (lane >> 2)]);
    }
    float4* dst = reinterpret_cast<float4*>(
        Bf + (size_t)z * Kdst * HW + (((size_t)k8g * NB64 + nb) * 32 + lane) * 16);
#pragma unroll
    for (int q = 0; q < 4; q++)
        dst[q] = make_float4(v[q*4], v[q*4+1], v[q*4+2], v[q*4+3]);
}

// ---------------------------------------------------------------------------
// Fragment-direct TF32 GEMM: O[b] (384 x HW) = A(384 x K) @ B[b](K x HW)
// No shared memory; operands pre-swizzled fragment-major. 8 warps of 64x64,
// CTA tile 128x256, software pipeline depth 2 in registers.
// grid = (HW/256, 384/128, BATCH), block = 256.
// ---------------------------------------------------------------------------
__global__ __launch_bounds__(256, 1) void mmagemm_k(
    const float* __restrict__ Af, int Mblks,
    const float* __restrict__ Bf, int K,
    float* __restrict__ O)
{
    const int tid  = threadIdx.x;
    const int wid  = tid >> 5;
    const int lane = tid & 31;
    const int wm = (wid & 1) * 64;
    const int wn = (wid >> 1) * 64;

    const int mBase = blockIdx.y * 128;
    const int nBase = blockIdx.x * 256;
    const int m64 = (mBase >> 6) + (wid & 1);
    const int nb  = (nBase >> 6) + (wid >> 1);

    const float4* Ap = reinterpret_cast<const float4*>(
        Af + (((size_t)0 * Mblks + m64) * 32 + lane) * 16);
    const float4* Bp = reinterpret_cast<const float4*>(
        Bf + (size_t)blockIdx.z * K * HW + (((size_t)0 * NB64 + nb) * 32 + lane) * 16);
    const size_t astep = (size_t)Mblks * 128;   // float4s per k8 slab
    const size_t bstep = (size_t)NB64 * 128;

    float* Ob = O + (size_t)blockIdx.z * CDIM * HW + (size_t)mBase * HW + nBase;

    float acc[4][8][4];
#pragma unroll
    for (int i = 0; i < 4; i++)
#pragma unroll
        for (int j = 0; j < 8; j++)
#pragma unroll
            for (int r = 0; r < 4; r++) acc[i][j][r] = 0.f;

    const int nk8 = K >> 3;
    float4 fa[2][4], fb[2][4];

#pragma unroll
    for (int q = 0; q < 4; q++){ fa[0][q] = Ap[q]; fb[0][q] = Bp[q]; }

#pragma unroll 2
    for (int k8 = 0; k8 < nk8; k8++){
        const int cur = k8 & 1, nxt = cur ^ 1;
        if (k8 + 1 < nk8){
            const float4* An = Ap + (size_t)(k8 + 1) * astep;
            const float4* Bn = Bp + (size_t)(k8 + 1) * bstep;
#pragma unroll
            for (int q = 0; q < 4; q++){ fa[nxt][q] = An[q]; fb[nxt][q] = Bn[q]; }
        }
#pragma unroll
        for (int mt = 0; mt < 4; mt++){
            const float4 a = fa[cur][mt];
#pragma unroll
            for (int np = 0; np < 4; np++){
                const float4 b = fb[cur][np];
                mma_tf32(acc[mt][np*2+0], a.x, a.y, a.z, a.w, b.x, b.y);
                mma_tf32(acc[mt][np*2+1], a.x, a.y, a.z, a.w, b.z, b.w);
            }
        }
    }

    const int r = lane >> 2;
    const int c2 = (lane & 3) * 2;
#pragma unroll
    for (int mt = 0; mt < 4; mt++){
        int row0 = wm + mt * 16 + r;
#pragma unroll
        for (int nt = 0; nt < 8; nt++){
            int col = wn + nt * 8 + c2;
            *reinterpret_cast<float2*>(&Ob[(size_t)row0 * HW + col]) =
                make_float2(acc[mt][nt][0], acc[mt][nt][1]);
            *reinterpret_cast<float2*>(&Ob[(size_t)(row0 + 8) * HW + col]) =
                make_float2(acc[mt][nt][2], acc[mt][nt][3]);
        }
    }
}

// ---------------------------------------------------------------------------
// Depthwise 3x3 SAME. grid = (4 strips, 1536 planes), block = 256
// ---------------------------------------------------------------------------
__global__ __launch_bounds__(256) void dw3x3_k(
    const float* __restrict__ in, const float* __restrict__ wdw,
    float* __restrict__ out)
{
    __shared__ float s[34 * 128];
    const int plane = blockIdx.y;
    const int c = plane % CDIM;
    const int y0 = blockIdx.x * 32;
    const float* ip = in + (size_t)plane * HW;
    float*       op = out + (size_t)plane * HW;

    for (int i = threadIdx.x; i < 34 * 32; i += 256) {
        int r  = i >> 5;
        int xq = (i & 31) << 2;
        int y  = y0 - 1 + r;
        float4 v = make_float4(0.f, 0.f, 0.f, 0.f);
        if (y >= 0 && y < HDIM)
            v = *reinterpret_cast<const float4*>(&ip[y * WDIM + xq]);
        *reinterpret_cast<float4*>(&s[r * 128 + xq]) = v;
    }
    float w[9];
#pragma unroll
    for (int j = 0; j < 9; j++) w[j] = wdw[c * 9 + j];
    __syncthreads();

    for (int i = threadIdx.x; i < 32 * 128; i += 256) {
        int ry = i >> 7;
        int x  = i & 127;
        float acc = 0.f;
#pragma unroll
        for (int dy = 0; dy < 3; dy++) {
#pragma unroll
            for (int dx = -1; dx <= 1; dx++) {
                int xx = x + dx;
                if (xx >= 0 && xx < WDIM)
                    acc += w[dy * 3 + (dx + 1)] * s[(ry + dy) * 128 + xx];
            }
        }
        op[(y0 + ry) * WDIM + x] = acc;
    }
}

// ---------------------------------------------------------------------------
__global__ __launch_bounds__(256) void rownorm_k(
    const float* __restrict__ q, const float* __restrict__ k,
    float* __restrict__ norms)
{
    const float* p = ((blockIdx.y == 0) ? q : k) + (size_t)blockIdx.x * HW;
    float s = 0.f;
    for (int i = threadIdx.x; i < HW / 4; i += 256) {
        float4 v = *reinterpret_cast<const float4*>(&p[i * 4]);
        s += v.x * v.x + v.y * v.y + v.z * v.z + v.w * v.w;
    }
#pragma unroll
    for (int o = 16; o; o >>= 1) s += __shfl_xor_sync(0xFFFFFFFFu, s, o);
    __shared__ float red[8];
    if ((threadIdx.x & 31) == 0) red[threadIdx.x >> 5] = s;
    __syncthreads();
    if (threadIdx.x == 0) {
        float t = 0.f;
#pragma unroll
        for (int i = 0; i < 8; i++) t += red[i];
        norms[blockIdx.y * NPLANE + blockIdx.x] = fmaxf(sqrtf(t), 1e-12f);
    }
}

// ---------------------------------------------------------------------------
__global__ __launch_bounds__(256) void gram_k(
    const float* __restrict__ q, const float* __restrict__ k,
    float* __restrict__ Gpart)
{
    __shared__ float sq[CH * 64];
    __shared__ float sk[CH * 64];
    const int bh = blockIdx.y;
    const size_t base = (size_t)bh * CH * HW;
    const float* qp = q + base;
    const float* kp = k + base;
    const int kstart = blockIdx.x * 1024;

    float acc[9];
#pragma unroll
    for (int i = 0; i < 9; i++) acc[i] = 0.f;

    for (int kt = kstart; kt < kstart + 1024; kt += 64) {
        for (int i = threadIdx.x; i < CH * 16; i += 256) {
            int r  = i >> 4;
            int xq = (i & 15) << 2;
            *reinterpret_cast<float4*>(&sq[r * 64 + xq]) =
                *reinterpret_cast<const float4*>(&qp[(size_t)r * HW + kt + xq]);
            *reinterpret_cast<float4*>(&sk[r * 64 + xq]) =
                *reinterpret_cast<const float4*>(&kp[(size_t)r * HW + kt + xq]);
        }
        __syncthreads();
#pragma unroll
        for (int pi = 0; pi < 9; pi++) {
            int p = threadIdx.x + pi * 256;
            int c = p / CH;
            int d = p - c * CH;
            float a = 0.f;
#pragma unroll 8
            for (int t = 0; t < 64; t++)
                a += sq[c * 64 + t] * sk[d * 64 + t];
            acc[pi] += a;
        }
        __syncthreads();
    }

    float* Gp = Gpart + ((size_t)blockIdx.x * 32 + bh) * (CH * CH);
#pragma unroll
    for (int pi = 0; pi < 9; pi++)
        Gp[threadIdx.x + pi * 256] = acc[pi];
}

// ---------------------------------------------------------------------------
__global__ void softmax_k(
    const float* __restrict__ Gpart, const float* __restrict__ norms,
    const float* __restrict__ temp, float* __restrict__ attn)
{
    int row = blockIdx.x * blockDim.x + threadIdx.x;
    if (row >= NPLANE) return;
    int bh = row / CH;
    int c  = row - bh * CH;
    int h  = bh & 7;
    float nq = norms[row];
    float tv = temp[h];

    float vals[CH];
    float vmax = -3.4e38f;
#pragma unroll
    for (int d = 0; d < CH; d++) {
        float g = 0.f;
        for (int s = 0; s < 16; s++)
            g += Gpart[((size_t)s * 32 + bh) * (CH * CH) + c * CH + d];
        float nk = norms[NPLANE + bh * CH + d];
        float v = g / (nq * nk) * tv;
        vals[d] = v;
        vmax = fmaxf(vmax, v);
    }
    float sum = 0.f;
#pragma unroll
    for (int d = 0; d < CH; d++) {
        vals[d] = expf(vals[d] - vmax);
        sum += vals[d];
    }
    float inv = 1.f / sum;
#pragma unroll
    for (int d = 0; d < CH; d++)
        attn[(size_t)bh * (CH * CH) + c * CH + d] = vals[d] * inv;
}

// ---------------------------------------------------------------------------
__global__ __launch_bounds__(256) void attnv_k(
    const float* __restrict__ attn, const float* __restrict__ v,
    float* __restrict__ out)
{
    __shared__ float sA[CH * CH];
    const int bh = blockIdx.y;
    const float* Ab = attn + (size_t)bh * (CH * CH);
    for (int i = threadIdx.x; i < CH * CH; i += 256) sA[i] = Ab[i];
    __syncthreads();

    const size_t base = (size_t)bh * CH * HW;
    const float* vp = v + base;
    float*       op = out + base;
    const int n0 = blockIdx.x * 512 + threadIdx.x;
    const int n1 = n0 + 256;

    float a0[CH], a1[CH];
#pragma unroll
    for (int cc = 0; cc < CH; cc++) { a0[cc] = 0.f; a1[cc] = 0.f; }

    for (int d = 0; d < CH; d++) {
        float v0 = vp[(size_t)d * HW + n0];
        float v1 = vp[(size_t)d * HW + n1];
#pragma unroll
        for (int cc = 0; cc < CH; cc++) {
            float a = sA[cc * CH + d];
            a0[cc] += a * v0;
            a1[cc] += a * v1;
        }
    }
#pragma unroll
    for (int cc = 0; cc < CH; cc++) {
        op[(size_t)cc * HW + n0] = a0[cc];
        op[(size_t)cc * HW + n1] = a1[cc];
    }
}

// ---------------------------------------------------------------------------
extern "C" void kernel_launch(void* const* d_in, const int* in_sizes, int n_in,
                              void* d_out, int out_size)
{
    const float* x       = (const float*)d_in[0];
    const float* t       = (const float*)d_in[1];
    const float* w_q     = (const float*)d_in[2];
    const float* w_q_dw  = (const float*)d_in[3];
    const float* w_qT    = (const float*)d_in[4];
    const float* w_qT_dw = (const float*)d_in[5];
    const float* w_qcat  = (const float*)d_in[6];
    const float* w_k     = (const float*)d_in[7];
    const float* w_k_dw  = (const float*)d_in[8];
    const float* w_v     = (const float*)d_in[9];
    const float* w_v_dw  = (const float*)d_in[10];
    const float* temp    = (const float*)d_in[11];
    float* out = (float*)d_out;

    float *bA, *bB, *bC, *bD, *xf, *tf, *qqf, *wf, *nrm, *gp, *at;
    cudaGetSymbolAddress((void**)&bA, g_bufA);
    cudaGetSymbolAddress((void**)&bB, g_bufB);
    cudaGetSymbolAddress((void**)&bC, g_bufC);
    cudaGetSymbolAddress((void**)&bD, g_bufD);
    cudaGetSymbolAddress((void**)&xf, g_Xf);
    cudaGetSymbolAddress((void**)&tf, g_Tf);
    cudaGetSymbolAddress((void**)&qqf, g_QQf);
    cudaGetSymbolAddress((void**)&wf, g_Wf);
    cudaGetSymbolAddress((void**)&nrm, g_norms);
    cudaGetSymbolAddress((void**)&gp, g_gpart);
    cudaGetSymbolAddress((void**)&at, g_attn);

    dim3 gG(HW / 256, CDIM / 128, BATCH);     // (64, 3, 4)
    dim3 gDw(4, NPLANE);
    dim3 gNorm(NPLANE, 2);
    dim3 gGram(16, 32);
    dim3 gAv(HW / 512, 32);
    dim3 gW(CDIM / 8, CDIM / 64);              // (48, 6)
    dim3 gW2(2 * CDIM / 8, CDIM / 64);         // (96, 6) for qcat (K=768)
    dim3 gBF(HW / 512, CDIM / 8, BATCH);       // (32, 48, 4)

    // weight fragments (tiny)
    prep_w_k<<<gW,  32>>>(w_q,    CDIM,     CDIM / 64, wf + WOFF_Q);
    prep_w_k<<<gW,  32>>>(w_qT,   CDIM,     CDIM / 64, wf + WOFF_QT);
    prep_w_k<<<gW2, 32>>>(w_qcat, 2 * CDIM, CDIM / 64, wf + WOFF_QCAT);
    prep_w_k<<<gW,  32>>>(w_k,    CDIM,     CDIM / 64, wf + WOFF_K);
    prep_w_k<<<gW,  32>>>(w_v,    CDIM,     CDIM / 64, wf + WOFF_V);

    // input fragments
    prep_bfrag_k<<<gBF, 256>>>(x, CDIM, xf, CDIM, 0);
    prep_bfrag_k<<<gBF, 256>>>(t, CDIM, tf, CDIM, 0);

    // q1 = dw(pw(x, w_q)); fragment into QQf[k8 0..47]
    mmagemm_k<<<gG, 256>>>(wf + WOFF_Q, CDIM / 64, xf, CDIM, bA);
    dw3x3_k<<<gDw, 256>>>(bA, w_q_dw, bB);
    prep_bfrag_k<<<gBF, 256>>>(bB, CDIM, qqf, 2 * CDIM, 0);

    // q2 = dw(pw(t, w_qT)); fragment into QQf[k8 48..95]
    mmagemm_k<<<gG, 256>>>(wf + WOFF_QT, CDIM / 64, tf, CDIM, bA);
    dw3x3_k<<<gDw, 256>>>(bA, w_qT_dw, bB);
    prep_bfrag_k<<<gBF, 256>>>(bB, CDIM, qqf, 2 * CDIM, CDIM / 8);

    // q = w_qcat @ concat  (K=768)
    mmagemm_k<<<gG, 256>>>(wf + WOFF_QCAT, CDIM / 64, qqf, 2 * CDIM, bD);

    // k, v
    mmagemm_k<<<gG, 256>>>(wf + WOFF_K, CDIM / 64, xf, CDIM, bA);
    dw3x3_k<<<gDw, 256>>>(bA, w_k_dw, bB);
    mmagemm_k<<<gG, 256>>>(wf + WOFF_V, CDIM / 64, xf, CDIM, bA);
    dw3x3_k<<<gDw, 256>>>(bA, w_v_dw, bC);

    // attention tail (fp32)
    rownorm_k<<<gNorm, 256>>>(bD, bB, nrm);
    gram_k<<<gGram, 256>>>(bD, bB, gp);
    softmax_k<<<12, 128>>>(gp, nrm, temp, at);
    attnv_k<<<gAv, 256>>>(at, bC, out);
}

// round 6
// speedup vs baseline: 1.2060x; 1.2060x over previous
#include <cuda_runtime.h>
#include <cuda_fp16.h>
#include <cstdint>
#include <math.h>

#define BATCH 4
#define CDIM 384
#define HDIM 128
#define WDIM 128
#define HW 16384
#define HEADS 8
#define CH 48
#define NPLANE (BATCH*CDIM)
#define NELEM (BATCH*CDIM*HW)
#define NB64 (HW/64)        // 256 n-blocks of 64

// ---------------- static device scratch (no cudaMalloc allowed) -------------
__device__ float g_bufA[NELEM];      // gemm output (std layout)
__device__ float g_bufB[NELEM];      // dw temp / k std
__device__ float g_bufC[NELEM];      // v std
__device__ float g_bufD[NELEM];      // q std
__device__ __half g_Xf[NELEM];       // x fragment-major fp16
__device__ __half g_Tf[NELEM];       // t fragment-major fp16
__device__ __half g_QQf[2*NELEM];    // concat(q1,q2) fragment-major fp16 (K=768)
__device__ __half g_Wf[4*CDIM*CDIM + CDIM*2*CDIM];
__device__ float g_norms[2*NPLANE];
__device__ float g_gpart[16*32*CH*CH];
__device__ float g_attn[32*CH*CH];

// Wf offsets (halves)
#define WOFF_Q    0
#define WOFF_QT   (CDIM*CDIM)
#define WOFF_QCAT (2*CDIM*CDIM)
#define WOFF_K    (2*CDIM*CDIM + CDIM*2*CDIM)
#define WOFF_V    (3*CDIM*CDIM + CDIM*2*CDIM)

// ---------------- helpers ---------------------------------------------------
__device__ __forceinline__ void mma_f16(float* c, uint32_t a0, uint32_t a1,
                                        uint32_t a2, uint32_t a3,
                                        uint32_t b0, uint32_t b1){
    asm volatile(
        "mma.sync.aligned.m16n8k16.row.col.f32.f16.f16.f32 "
        "{%0,%1,%2,%3}, {%4,%5,%6,%7}, {%8,%9}, {%0,%1,%2,%3};"
        : "+f"(c[0]), "+f"(c[1]), "+f"(c[2]), "+f"(c[3])
        : "r"(a0), "r"(a1), "r"(a2), "r"(a3), "r"(b0), "r"(b1));
}

// ---------------------------------------------------------------------------
// Weight -> fp16 A-fragment layout (m16n8k16 row-major A).
// Per (k16, mb, lane): 4 m-tiles x 4 b32 regs (each reg = half2 of cols j=0,1):
//   reg r (0..3): row = mb*64 + mt*16 + (lane>>2) + (r&1)*8
//                 col = k16*16 + (lane&3)*2 + j + ((r>>1)&1)*8
// Stored as 4 float4 per lane: float4 mt = {a0,a1,a2,a3}.
// grid = (K/16, M/64), block = 32
// ---------------------------------------------------------------------------
__global__ void prep_w_k(const float* __restrict__ W, int ldk, int Mblks,
                         __half* __restrict__ Af)
{
    const int k16 = blockIdx.x, mb = blockIdx.y, lane = threadIdx.x;
    uint32_t regs[4][4];
#pragma unroll
    for (int mt = 0; mt < 4; mt++){
#pragma unroll
        for (int r = 0; r < 4; r++){
            int row = mb * 64 + mt * 16 + (lane >> 2) + (r & 1) * 8;
            int col = k16 * 16 + (lane & 3) * 2 + ((r >> 1) & 1) * 8;
            __half2 h = __floats2half2_rn(W[(size_t)row * ldk + col],
                                          W[(size_t)row * ldk + col + 1]);
            regs[mt][r] = *reinterpret_cast<uint32_t*>(&h);
        }
    }
    uint4* dst = reinterpret_cast<uint4*>(
        Af + ((((size_t)k16 * Mblks + mb) * 32 + lane) * 32));
#pragma unroll
    for (int mt = 0; mt < 4; mt++)
        dst[mt] = make_uint4(regs[mt][0], regs[mt][1], regs[mt][2], regs[mt][3]);
}

// ---------------------------------------------------------------------------
// Std [K'][HW] (per batch) -> fp16 B-fragment layout (m16n8k16 col-major B).
// Per (k16, nb, lane): 8 n-tiles x 2 b32 regs (reg = half2 of k j=0,1):
//   reg r (0..1): k = k16*16 + (lane&3)*2 + j + r*8
//                 n = nb*64 + nt*8 + (lane>>2)
// Stored as 4 float4: float4 q = {b0(nt=2q), b1(nt=2q), b0(nt=2q+1), b1(nt=2q+1)}.
// Block: one k16 slab x 512 cols. grid = (HW/512, K'/16, BATCH), blk 256.
// ---------------------------------------------------------------------------
__global__ __launch_bounds__(256) void prep_bfrag_k(
    const float* __restrict__ src, int Ksrc,
    __half* __restrict__ Bf, int Kdst, int k16base)
{
    __shared__ float s[16 * 520];
    const int tid = threadIdx.x;
    const int z = blockIdx.z;
    const int k16l = blockIdx.y;
    const int n0 = blockIdx.x * 512;
    const float* sp = src + (size_t)z * Ksrc * HW + (size_t)(k16l * 16) * HW + n0;

#pragma unroll
    for (int i = 0; i < 8; i++){
        int f = tid + i * 256;       // 2048 float4
        int r = f >> 7;
        int c4 = (f & 127) << 2;
        *reinterpret_cast<float4*>(&s[r * 520 + c4]) =
            *reinterpret_cast<const float4*>(&sp[(size_t)r * HW + c4]);
    }
    __syncthreads();

    const int w = tid >> 5, lane = tid & 31;
    const int k16g = k16base + k16l;
    const int nb = (n0 >> 6) + w;
    uint32_t regs[8][2];
#pragma unroll
    for (int nt = 0; nt < 8; nt++){
        int n_l = w * 64 + nt * 8 + (lane >> 2);
#pragma unroll
        for (int r = 0; r < 2; r++){
            int k_l = (lane & 3) * 2 + r * 8;
            __half2 h = __floats2half2_rn(s[k_l * 520 + n_l],
                                          s[(k_l + 1) * 520 + n_l]);
            regs[nt][r] = *reinterpret_cast<uint32_t*>(&h);
        }
    }
    uint4* dst = reinterpret_cast<uint4*>(
        Bf + (size_t)z * Kdst * HW + ((((size_t)k16g * NB64 + nb) * 32 + lane) * 32));
#pragma unroll
    for (int q = 0; q < 4; q++)
        dst[q] = make_uint4(regs[q*2][0], regs[q*2][1], regs[q*2+1][0], regs[q*2+1][1]);
}

// ---------------------------------------------------------------------------
// Fragment-direct FP16 GEMM: O[b] (384 x HW) = A(384 x K) @ B[b](K x HW)
// 8 warps of 64x64, CTA tile 128x256, reg pipeline depth 2.
// grid = (HW/256, 384/128, BATCH), block = 256.
// ---------------------------------------------------------------------------
__global__ __launch_bounds__(256, 1) void mmagemm_k(
    const __half* __restrict__ Af, int Mblks,
    const __half* __restrict__ Bf, int K,
    float* __restrict__ O)
{
    const int tid  = threadIdx.x;
    const int wid  = tid >> 5;
    const int lane = tid & 31;
    const int wm = (wid & 1) * 64;
    const int wn = (wid >> 1) * 64;

    const int mBase = blockIdx.y * 128;
    const int nBase = blockIdx.x * 256;
    const int m64 = (mBase >> 6) + (wid & 1);
    const int nb  = (nBase >> 6) + (wid >> 1);

    const uint4* Ap = reinterpret_cast<const uint4*>(
        Af + (((size_t)m64) * 32 + lane) * 32);
    const uint4* Bp = reinterpret_cast<const uint4*>(
        Bf + (size_t)blockIdx.z * K * HW + (((size_t)nb) * 32 + lane) * 32);
    const size_t astep = (size_t)Mblks * 128;   // uint4s per k16 slab
    const size_t bstep = (size_t)NB64 * 128;

    float* Ob = O + (size_t)blockIdx.z * CDIM * HW + (size_t)mBase * HW + nBase;

    float acc[4][8][4];
#pragma unroll
    for (int i = 0; i < 4; i++)
#pragma unroll
        for (int j = 0; j < 8; j++)
#pragma unroll
            for (int r = 0; r < 4; r++) acc[i][j][r] = 0.f;

    const int nk16 = K >> 4;
    uint4 fa[2][4], fb[2][4];

#pragma unroll
    for (int q = 0; q < 4; q++){ fa[0][q] = Ap[q]; fb[0][q] = Bp[q]; }

#pragma unroll 2
    for (int k16 = 0; k16 < nk16; k16++){
        const int cur = k16 & 1, nxt = cur ^ 1;
        if (k16 + 1 < nk16){
            const uint4* An = Ap + (size_t)(k16 + 1) * astep;
            const uint4* Bn = Bp + (size_t)(k16 + 1) * bstep;
#pragma unroll
            for (int q = 0; q < 4; q++){ fa[nxt][q] = An[q]; fb[nxt][q] = Bn[q]; }
        }
#pragma unroll
        for (int mt = 0; mt < 4; mt++){
            const uint4 a = fa[cur][mt];
#pragma unroll
            for (int np = 0; np < 4; np++){
                const uint4 b = fb[cur][np];
                mma_f16(acc[mt][np*2+0], a.x, a.y, a.z, a.w, b.x, b.y);
                mma_f16(acc[mt][np*2+1], a.x, a.y, a.z, a.w, b.z, b.w);
            }
        }
    }

    const int r = lane >> 2;
    const int c2 = (lane & 3) * 2;
#pragma unroll
    for (int mt = 0; mt < 4; mt++){
        int row0 = wm + mt * 16 + r;
#pragma unroll
        for (int nt = 0; nt < 8; nt++){
            int col = wn + nt * 8 + c2;
            *reinterpret_cast<float2*>(&Ob[(size_t)row0 * HW + col]) =
                make_float2(acc[mt][nt][0], acc[mt][nt][1]);
            *reinterpret_cast<float2*>(&Ob[(size_t)(row0 + 8) * HW + col]) =
                make_float2(acc[mt][nt][2], acc[mt][nt][3]);
        }
    }
}

// ---------------------------------------------------------------------------
// Depthwise 3x3 SAME. grid = (4 strips, 1536 planes), block = 256
// ---------------------------------------------------------------------------
__global__ __launch_bounds__(256) void dw3x3_k(
    const float* __restrict__ in, const float* __restrict__ wdw,
    float* __restrict__ out)
{
    __shared__ float s[34 * 128];
    const int plane = blockIdx.y;
    const int c = plane % CDIM;
    const int y0 = blockIdx.x * 32;
    const float* ip = in + (size_t)plane * HW;
    float*       op = out + (size_t)plane * HW;

    for (int i = threadIdx.x; i < 34 * 32; i += 256) {
        int r  = i >> 5;
        int xq = (i & 31) << 2;
        int y  = y0 - 1 + r;
        float4 v = make_float4(0.f, 0.f, 0.f, 0.f);
        if (y >= 0 && y < HDIM)
            v = *reinterpret_cast<const float4*>(&ip[y * WDIM + xq]);
        *reinterpret_cast<float4*>(&s[r * 128 + xq]) = v;
    }
    float w[9];
#pragma unroll
    for (int j = 0; j < 9; j++) w[j] = wdw[c * 9 + j];
    __syncthreads();

    for (int i = threadIdx.x; i < 32 * 128; i += 256) {
        int ry = i >> 7;
        int x  = i & 127;
        float acc = 0.f;
#pragma unroll
        for (int dy = 0; dy < 3; dy++) {
#pragma unroll
            for (int dx = -1; dx <= 1; dx++) {
                int xx = x + dx;
                if (xx >= 0 && xx < WDIM)
                    acc += w[dy * 3 + (dx + 1)] * s[(ry + dy) * 128 + xx];
            }
        }
        op[(y0 + ry) * WDIM + x] = acc;
    }
}

// ---------------------------------------------------------------------------
__global__ __launch_bounds__(256) void rownorm_k(
    const float* __restrict__ q, const float* __restrict__ k,
    float* __restrict__ norms)
{
    const float* p = ((blockIdx.y == 0) ? q : k) + (size_t)blockIdx.x * HW;
    float s = 0.f;
    for (int i = threadIdx.x; i < HW / 4; i += 256) {
        float4 v = *reinterpret_cast<const float4*>(&p[i * 4]);
        s += v.x * v.x + v.y * v.y + v.z * v.z + v.w * v.w;
    }
#pragma unroll
    for (int o = 16; o; o >>= 1) s += __shfl_xor_sync(0xFFFFFFFFu, s, o);
    __shared__ float red[8];
    if ((threadIdx.x & 31) == 0) red[threadIdx.x >> 5] = s;
    __syncthreads();
    if (threadIdx.x == 0) {
        float t = 0.f;
#pragma unroll
        for (int i = 0; i < 8; i++) t += red[i];
        norms[blockIdx.y * NPLANE + blockIdx.x] = fmaxf(sqrtf(t), 1e-12f);
    }
}

// ---------------------------------------------------------------------------
__global__ __launch_bounds__(256) void gram_k(
    const float* __restrict__ q, const float* __restrict__ k,
    float* __restrict__ Gpart)
{
    __shared__ float sq[CH * 64];
    __shared__ float sk[CH * 64];
    const int bh = blockIdx.y;
    const size_t base = (size_t)bh * CH * HW;
    const float* qp = q + base;
    const float* kp = k + base;
    const int kstart = blockIdx.x * 1024;

    float acc[9];
#pragma unroll
    for (int i = 0; i < 9; i++) acc[i] = 0.f;

    for (int kt = kstart; kt < kstart + 1024; kt += 64) {
        for (int i = threadIdx.x; i < CH * 16; i += 256) {
            int r  = i >> 4;
            int xq = (i & 15) << 2;
            *reinterpret_cast<float4*>(&sq[r * 64 + xq]) =
                *reinterpret_cast<const float4*>(&qp[(size_t)r * HW + kt + xq]);
            *reinterpret_cast<float4*>(&sk[r * 64 + xq]) =
                *reinterpret_cast<const float4*>(&kp[(size_t)r * HW + kt + xq]);
        }
        __syncthreads();
#pragma unroll
        for (int pi = 0; pi < 9; pi++) {
            int p = threadIdx.x + pi * 256;
            int c = p / CH;
            int d = p - c * CH;
            float a = 0.f;
#pragma unroll 8
            for (int t = 0; t < 64; t++)
                a += sq[c * 64 + t] * sk[d * 64 + t];
            acc[pi] += a;
        }
        __syncthreads();
    }

    float* Gp = Gpart + ((size_t)blockIdx.x * 32 + bh) * (CH * CH);
#pragma unroll
    for (int pi = 0; pi < 9; pi++)
        Gp[threadIdx.x + pi * 256] = acc[pi];
}

// ---------------------------------------------------------------------------
__global__ void softmax_k(
    const float* __restrict__ Gpart, const float* __restrict__ norms,
    const float* __restrict__ temp, float* __restrict__ attn)
{
    int row = blockIdx.x * blockDim.x + threadIdx.x;
    if (row >= NPLANE) return;
    int bh = row / CH;
    int c  = row - bh * CH;
    int h  = bh & 7;
    float nq = norms[row];
    float tv = temp[h];

    float vals[CH];
    float vmax = -3.4e38f;
#pragma unroll
    for (int d = 0; d < CH; d++) {
        float g = 0.f;
        for (int s = 0; s < 16; s++)
            g += Gpart[((size_t)s * 32 + bh) * (CH * CH) + c * CH + d];
        float nk = norms[NPLANE + bh * CH + d];
        float v = g / (nq * nk) * tv;
        vals[d] = v;
        vmax = fmaxf(vmax, v);
    }
    float sum = 0.f;
#pragma unroll
    for (int d = 0; d < CH; d++) {
        vals[d] = expf(vals[d] - vmax);
        sum += vals[d];
    }
    float inv = 1.f / sum;
#pragma unroll
    for (int d = 0; d < CH; d++)
        attn[(size_t)bh * (CH * CH) + c * CH + d] = vals[d] * inv;
}

// ---------------------------------------------------------------------------
__global__ __launch_bounds__(256) void attnv_k(
    const float* __restrict__ attn, const float* __restrict__ v,
    float* __restrict__ out)
{
    __shared__ float sA[CH * CH];
    const int bh = blockIdx.y;
    const float* Ab = attn + (size_t)bh * (CH * CH);
    for (int i = threadIdx.x; i < CH * CH; i += 256) sA[i] = Ab[i];
    __syncthreads();

    const size_t base = (size_t)bh * CH * HW;
    const float* vp = v + base;
    float*       op = out + base;
    const int n0 = blockIdx.x * 512 + threadIdx.x;
    const int n1 = n0 + 256;

    float a0[CH], a1[CH];
#pragma unroll
    for (int cc = 0; cc < CH; cc++) { a0[cc] = 0.f; a1[cc] = 0.f; }

    for (int d = 0; d < CH; d++) {
        float v0 = vp[(size_t)d * HW + n0];
        float v1 = vp[(size_t)d * HW + n1];
#pragma unroll
        for (int cc = 0; cc < CH; cc++) {
            float a = sA[cc * CH + d];
            a0[cc] += a * v0;
            a1[cc] += a * v1;
        }
    }
#pragma unroll
    for (int cc = 0; cc < CH; cc++) {
        op[(size_t)cc * HW + n0] = a0[cc];
        op[(size_t)cc * HW + n1] = a1[cc];
    }
}

// ---------------------------------------------------------------------------
extern "C" void kernel_launch(void* const* d_in, const int* in_sizes, int n_in,
                              void* d_out, int out_size)
{
    const float* x       = (const float*)d_in[0];
    const float* t       = (const float*)d_in[1];
    const float* w_q     = (const float*)d_in[2];
    const float* w_q_dw  = (const float*)d_in[3];
    const float* w_qT    = (const float*)d_in[4];
    const float* w_qT_dw = (const float*)d_in[5];
    const float* w_qcat  = (const float*)d_in[6];
    const float* w_k     = (const float*)d_in[7];
    const float* w_k_dw  = (const float*)d_in[8];
    const float* w_v     = (const float*)d_in[9];
    const float* w_v_dw  = (const float*)d_in[10];
    const float* temp    = (const float*)d_in[11];
    float* out = (float*)d_out;

    float *bA, *bB, *bC, *bD, *nrm, *gp, *at;
    __half *xf, *tf, *qqf, *wf;
    cudaGetSymbolAddress((void**)&bA, g_bufA);
    cudaGetSymbolAddress((void**)&bB, g_bufB);
    cudaGetSymbolAddress((void**)&bC, g_bufC);
    cudaGetSymbolAddress((void**)&bD, g_bufD);
    cudaGetSymbolAddress((void**)&xf, g_Xf);
    cudaGetSymbolAddress((void**)&tf, g_Tf);
    cudaGetSymbolAddress((void**)&qqf, g_QQf);
    cudaGetSymbolAddress((void**)&wf, g_Wf);
    cudaGetSymbolAddress((void**)&nrm, g_norms);
    cudaGetSymbolAddress((void**)&gp, g_gpart);
    cudaGetSymbolAddress((void**)&at, g_attn);

    dim3 gG(HW / 256, CDIM / 128, BATCH);      // (64, 3, 4)
    dim3 gDw(4, NPLANE);
    dim3 gNorm(NPLANE, 2);
    dim3 gGram(16, 32);
    dim3 gAv(HW / 512, 32);
    dim3 gW(CDIM / 16, CDIM / 64);             // (24, 6)
    dim3 gW2(2 * CDIM / 16, CDIM / 64);        // (48, 6) for qcat (K=768)
    dim3 gBF(HW / 512, CDIM / 16, BATCH);      // (32, 24, 4)

    // weight fragments (tiny)
    prep_w_k<<<gW,  32>>>(w_q,    CDIM,     CDIM / 64, wf + WOFF_Q);
    prep_w_k<<<gW,  32>>>(w_qT,   CDIM,     CDIM / 64, wf + WOFF_QT);
    prep_w_k<<<gW2, 32>>>(w_qcat, 2 * CDIM, CDIM / 64, wf + WOFF_QCAT);
    prep_w_k<<<gW,  32>>>(w_k,    CDIM,     CDIM / 64, wf + WOFF_K);
    prep_w_k<<<gW,  32>>>(w_v,    CDIM,     CDIM / 64, wf + WOFF_V);

    // input fragments
    prep_bfrag_k<<<gBF, 256>>>(x, CDIM, xf, CDIM, 0);
    prep_bfrag_k<<<gBF, 256>>>(t, CDIM, tf, CDIM, 0);

    // q1 = dw(pw(x, w_q)); fragment into QQf[k16 0..23]
    mmagemm_k<<<gG, 256>>>(wf + WOFF_Q, CDIM / 64, xf, CDIM, bA);
    dw3x3_k<<<gDw, 256>>>(bA, w_q_dw, bB);
    prep_bfrag_k<<<gBF, 256>>>(bB, CDIM, qqf, 2 * CDIM, 0);

    // q2 = dw(pw(t, w_qT)); fragment into QQf[k16 24..47]
    mmagemm_k<<<gG, 256>>>(wf + WOFF_QT, CDIM / 64, tf, CDIM, bA);
    dw3x3_k<<<gDw, 256>>>(bA, w_qT_dw, bB);
    prep_bfrag_k<<<gBF, 256>>>(bB, CDIM, qqf, 2 * CDIM, CDIM / 16);

    // q = w_qcat @ concat  (K=768)
    mmagemm_k<<<gG, 256>>>(wf + WOFF_QCAT, CDIM / 64, qqf, 2 * CDIM, bD);

    // k, v
    mmagemm_k<<<gG, 256>>>(wf + WOFF_K, CDIM / 64, xf, CDIM, bA);
    dw3x3_k<<<gDw, 256>>>(bA, w_k_dw, bB);
    mmagemm_k<<<gG, 256>>>(wf + WOFF_V, CDIM / 64, xf, CDIM, bA);
    dw3x3_k<<<gDw, 256>>>(bA, w_v_dw, bC);

    // attention tail (fp32)
    rownorm_k<<<gNorm, 256>>>(bD, bB, nrm);
    gram_k<<<gGram, 256>>>(bD, bB, gp);
    softmax_k<<<12, 128>>>(gp, nrm, temp, at);
    attnv_k<<<gAv, 256>>>(at, bC, out);
}